// round 3
// baseline (speedup 1.0000x reference)
#include <cuda_runtime.h>
#include <cuda_bf16.h>

#define N_NODES 100000
#define EMB_DIM 128
#define HIDDEN  64
#define N_EDGES 1600000

// Scratch: per-node precomputed [u | v], 128 floats per node (51.2 MB).
// u[h] = emb[n] . W1[0:128, h],  v[h] = emb[n] . W1[128:256, h]
__device__ float g_UV[(size_t)N_NODES * 128];

// 1 if edge_index is int64 on device, 0 if int32.
__device__ int g_idx_is_64;

// ---- packed f32x2 helpers (FFMA2 path, sm_103a) ----------------------------
__device__ __forceinline__ unsigned long long pack2(float x) {
    unsigned long long r;
    asm("mov.b64 %0, {%1, %1};" : "=l"(r) : "f"(x));
    return r;
}
__device__ __forceinline__ void ffma2(unsigned long long& d,
                                      unsigned long long a,
                                      unsigned long long b) {
    asm("fma.rn.f32x2 %0, %1, %2, %0;" : "+l"(d) : "l"(a), "l"(b));
}

// ---------------------------------------------------------------------------
// Kernel 1: UV[n][j] = sum_k emb[n][k] * Wc[k][j]
//   Wc[k][j] = W1[k][j]        for j <  64   (u half)
//   Wc[k][j] = W1[128+k][j-64] for j >= 64   (v half)
// One warp computes 8 nodes; lane owns 4 output cols (pair of f32x2 accums).
// Wc (128x128 fp32 = 64 KB) staged in dynamic shared memory per block.
// Block 0 additionally detects the edge_index dtype (int32 vs int64).
// ---------------------------------------------------------------------------
extern __shared__ float sW[];  // 128*128 floats

__global__ __launch_bounds__(256, 2)
void precompute_uv_kernel(const float* __restrict__ emb,
                          const float* __restrict__ W1,
                          const int* __restrict__ eidx32) {
    // --- dtype detection (block 0 only): if int64 with values < 2^31,
    // every odd 32-bit word is 0. Sample 128 odd-word positions. ---
    __shared__ int s_any;
    if (blockIdx.x == 0) {
        if (threadIdx.x == 0) s_any = 0;
        __syncthreads();
        if (threadIdx.x < 128) {
            int w = eidx32[2 * ((int)threadIdx.x * 37 + 1) + 1];
            if (w != 0) atomicOr(&s_any, 1);
        }
        __syncthreads();
        if (threadIdx.x == 0) g_idx_is_64 = (s_any == 0) ? 1 : 0;
    }

    // --- stage Wc into shared: W1 [256,64] row-major -> Wc [128,128] ---
    for (int i = threadIdx.x; i < 128 * 64; i += blockDim.x) {
        int k = i >> 6;          // 0..127
        int h = i & 63;          // 0..63
        sW[k * 128 + h]      = W1[k * 64 + h];
        sW[k * 128 + 64 + h] = W1[(128 + k) * 64 + h];
    }
    __syncthreads();

    int warp = (blockIdx.x * blockDim.x + threadIdx.x) >> 5;
    int lane = threadIdx.x & 31;
    int node0 = warp * 8;
    if (node0 >= N_NODES) return;

    // acc[n] = {cols 4*lane .. 4*lane+3} as two f32x2 pairs
    ulonglong2 acc[8];
    #pragma unroll
    for (int n = 0; n < 8; n++) { acc[n].x = 0ull; acc[n].y = 0ull; }

    const float* embp = emb + (size_t)node0 * EMB_DIM;

    for (int kc = 0; kc < 128; kc += 4) {
        float4 e[8];
        #pragma unroll
        for (int n = 0; n < 8; n++)
            e[n] = *(const float4*)(embp + n * EMB_DIM + kc);

        #pragma unroll
        for (int kk = 0; kk < 4; kk++) {
            ulonglong2 w = *(const ulonglong2*)(&sW[(kc + kk) * 128 + lane * 4]);
            #pragma unroll
            for (int n = 0; n < 8; n++) {
                float ev = (kk == 0) ? e[n].x : (kk == 1) ? e[n].y
                         : (kk == 2) ? e[n].z : e[n].w;
                unsigned long long evp = pack2(ev);
                ffma2(acc[n].x, evp, w.x);
                ffma2(acc[n].y, evp, w.y);
            }
        }
    }

    #pragma unroll
    for (int n = 0; n < 8; n++)
        *(ulonglong2*)(&g_UV[(size_t)(node0 + n) * 128 + lane * 4]) = acc[n];
}

// ---------------------------------------------------------------------------
// Kernel 2: per-edge score.
// 8 lanes per edge (4 edges/warp). Lane s owns cols s*8 .. s*8+7.
//   z = relu(u[src] + v[tgt] + b1);  score = z . W2 + b2
// Gathers are the hot path: 2 x 256 B per edge, served from L2 (UV fits).
// ---------------------------------------------------------------------------
__global__ __launch_bounds__(256)
void edge_score_kernel(const void* __restrict__ eidx_raw,
                       const float* __restrict__ b1,
                       const float* __restrict__ W2,
                       const float* __restrict__ b2,
                       float* __restrict__ out) {
    __shared__ float sb1[64];
    __shared__ float sw2[64];
    __shared__ float sb2;
    if (threadIdx.x < 64) {
        sb1[threadIdx.x] = b1[threadIdx.x];
        sw2[threadIdx.x] = W2[threadIdx.x];
    }
    if (threadIdx.x == 0) sb2 = b2[0];
    __syncthreads();

    int gtid = blockIdx.x * blockDim.x + threadIdx.x;
    int e = gtid >> 3;
    if (e >= N_EDGES) return;
    int s = threadIdx.x & 7;

    long long src, tgt;
    if (g_idx_is_64) {
        const long long* eidx = (const long long*)eidx_raw;
        src = eidx[e];
        tgt = eidx[N_EDGES + e];
    } else {
        const int* eidx = (const int*)eidx_raw;
        src = eidx[e];
        tgt = eidx[N_EDGES + e];
    }

    const float4* up = (const float4*)(g_UV + (size_t)src * 128) + s * 2;
    const float4* vp = (const float4*)(g_UV + (size_t)tgt * 128 + 64) + s * 2;
    float4 u0 = up[0], u1 = up[1];
    float4 v0 = vp[0], v1 = vp[1];

    float4 bb0 = *(const float4*)(sb1 + s * 8);
    float4 bb1 = *(const float4*)(sb1 + s * 8 + 4);
    float4 w0  = *(const float4*)(sw2 + s * 8);
    float4 w1  = *(const float4*)(sw2 + s * 8 + 4);

    float p = 0.f;
    {
        float z;
        z = fmaxf(u0.x + v0.x + bb0.x, 0.f); p = fmaf(z, w0.x, p);
        z = fmaxf(u0.y + v0.y + bb0.y, 0.f); p = fmaf(z, w0.y, p);
        z = fmaxf(u0.z + v0.z + bb0.z, 0.f); p = fmaf(z, w0.z, p);
        z = fmaxf(u0.w + v0.w + bb0.w, 0.f); p = fmaf(z, w0.w, p);
        z = fmaxf(u1.x + v1.x + bb1.x, 0.f); p = fmaf(z, w1.x, p);
        z = fmaxf(u1.y + v1.y + bb1.y, 0.f); p = fmaf(z, w1.y, p);
        z = fmaxf(u1.z + v1.z + bb1.z, 0.f); p = fmaf(z, w1.z, p);
        z = fmaxf(u1.w + v1.w + bb1.w, 0.f); p = fmaf(z, w1.w, p);
    }

    // reduce over the 8-lane group
    p += __shfl_xor_sync(0xFFFFFFFFu, p, 4);
    p += __shfl_xor_sync(0xFFFFFFFFu, p, 2);
    p += __shfl_xor_sync(0xFFFFFFFFu, p, 1);

    if (s == 0) out[e] = p + sb2;
}

// ---------------------------------------------------------------------------
extern "C" void kernel_launch(void* const* d_in, const int* in_sizes, int n_in,
                              void* d_out, int out_size) {
    const float* emb  = (const float*)d_in[0];
    const void*  eidx = d_in[1];
    const float* W1   = (const float*)d_in[2];
    const float* b1   = (const float*)d_in[3];
    const float* W2   = (const float*)d_in[4];
    const float* b2   = (const float*)d_in[5];
    float*       out  = (float*)d_out;

    cudaFuncSetAttribute(precompute_uv_kernel,
                         cudaFuncAttributeMaxDynamicSharedMemorySize,
                         128 * 128 * sizeof(float));

    // Kernel 1: 12500 warps (8 nodes each) -> 1563 blocks of 256 threads
    // (block 0 also detects the edge_index dtype)
    {
        int warps = (N_NODES + 7) / 8;
        int blocks = (warps * 32 + 255) / 256;
        precompute_uv_kernel<<<blocks, 256, 128 * 128 * sizeof(float)>>>(
            emb, W1, (const int*)eidx);
    }

    // Kernel 2: 8 threads per edge
    {
        long long threads = (long long)N_EDGES * 8;
        int blocks = (int)((threads + 255) / 256);
        edge_score_kernel<<<blocks, 256>>>(eidx, b1, W2, b2, out);
    }
}

// round 5
// speedup vs baseline: 1.9846x; 1.9846x over previous
#include <cuda_runtime.h>
#include <cuda_bf16.h>

#define N_NODES 100000
#define EMB_DIM 128
#define HIDDEN  64
#define N_EDGES 1600000

// Scratch: per-node precomputed [u | v], 128 floats per node (51.2 MB).
// u[h] = emb[n] . W1[0:128, h],  v[h] = emb[n] . W1[128:256, h]
__device__ float g_UV[(size_t)N_NODES * 128];

// 1 if edge_index is int64 on device, 0 if int32.
__device__ int g_idx_is_64;

// ---------------------------------------------------------------------------
// Kernel 1: UV[n][j] = sum_k emb[n][k] * Wc[k][j]
//   Wc[k][j] = W1[k][j]        for j <  64   (u half)
//   Wc[k][j] = W1[128+k][j-64] for j >= 64   (v half)
// One warp computes 8 nodes; lane owns 4 output cols (4*lane .. 4*lane+3).
// Wc (128x128 fp32 = 64 KB) staged in dynamic shared memory per block.
// Block 0 additionally detects the edge_index dtype (int32 vs int64).
// ---------------------------------------------------------------------------
extern __shared__ float sW[];  // 128*128 floats

__global__ __launch_bounds__(256)
void precompute_uv_kernel(const float* __restrict__ emb,
                          const float* __restrict__ W1,
                          const int* __restrict__ eidx32) {
    // --- dtype detection (block 0 only): if int64 with values < 2^31,
    // every odd 32-bit word is 0. Sample 128 odd-word positions. ---
    __shared__ int s_any;
    if (blockIdx.x == 0) {
        if (threadIdx.x == 0) s_any = 0;
        __syncthreads();
        if (threadIdx.x < 128) {
            int w = eidx32[2 * ((int)threadIdx.x * 37 + 1) + 1];
            if (w != 0) atomicOr(&s_any, 1);
        }
        __syncthreads();
        if (threadIdx.x == 0) g_idx_is_64 = (s_any == 0) ? 1 : 0;
    }

    // --- stage Wc into shared: W1 [256,64] row-major -> Wc [128,128] ---
    for (int i = threadIdx.x; i < 128 * 64; i += blockDim.x) {
        int k = i >> 6;          // 0..127
        int h = i & 63;          // 0..63
        sW[k * 128 + h]      = W1[k * 64 + h];
        sW[k * 128 + 64 + h] = W1[(128 + k) * 64 + h];
    }
    __syncthreads();

    int warp = (blockIdx.x * blockDim.x + threadIdx.x) >> 5;
    int lane = threadIdx.x & 31;
    int node0 = warp * 8;
    if (node0 >= N_NODES) return;

    float4 acc[8];
    #pragma unroll
    for (int n = 0; n < 8; n++) acc[n] = make_float4(0.f, 0.f, 0.f, 0.f);

    const float* embp = emb + (size_t)node0 * EMB_DIM;

    #pragma unroll 4
    for (int kc = 0; kc < 128; kc += 4) {
        float4 e[8];
        #pragma unroll
        for (int n = 0; n < 8; n++)
            e[n] = *(const float4*)(embp + n * EMB_DIM + kc);

        #pragma unroll
        for (int kk = 0; kk < 4; kk++) {
            float4 w = *(const float4*)(&sW[(kc + kk) * 128 + lane * 4]);
            #pragma unroll
            for (int n = 0; n < 8; n++) {
                float ev = (kk == 0) ? e[n].x : (kk == 1) ? e[n].y
                         : (kk == 2) ? e[n].z : e[n].w;
                acc[n].x = fmaf(ev, w.x, acc[n].x);
                acc[n].y = fmaf(ev, w.y, acc[n].y);
                acc[n].z = fmaf(ev, w.z, acc[n].z);
                acc[n].w = fmaf(ev, w.w, acc[n].w);
            }
        }
    }

    #pragma unroll
    for (int n = 0; n < 8; n++)
        *(float4*)(&g_UV[(size_t)(node0 + n) * 128 + lane * 4]) = acc[n];
}

// ---------------------------------------------------------------------------
// Kernel 2: per-edge score.
// 8 lanes per edge (4 edges/warp). Lane s owns cols {4s..4s+3, 32+4s..32+4s+3}
// so every LDG.128's 8-lane group covers exactly ONE contiguous 128B line:
//   u0 = urow[s]      (bytes [0,128)   of u half)  -> 1 line/edge
//   u1 = urow[8+s]    (bytes [128,256) of u half)  -> 1 line/edge
// (same for v). 4 wavefronts/edge instead of 8.
// ---------------------------------------------------------------------------
__global__ __launch_bounds__(256)
void edge_score_kernel(const void* __restrict__ eidx_raw,
                       const float* __restrict__ b1,
                       const float* __restrict__ W2,
                       const float* __restrict__ b2,
                       float* __restrict__ out) {
    __shared__ float sb1[64];
    __shared__ float sw2[64];
    __shared__ float sb2;
    if (threadIdx.x < 64) {
        sb1[threadIdx.x] = b1[threadIdx.x];
        sw2[threadIdx.x] = W2[threadIdx.x];
    }
    if (threadIdx.x == 0) sb2 = b2[0];
    __syncthreads();

    int gtid = blockIdx.x * blockDim.x + threadIdx.x;
    int e = gtid >> 3;
    if (e >= N_EDGES) return;
    int s = threadIdx.x & 7;

    long long src, tgt;
    if (g_idx_is_64) {
        const long long* eidx = (const long long*)eidx_raw;
        src = eidx[e];
        tgt = eidx[N_EDGES + e];
    } else {
        const int* eidx = (const int*)eidx_raw;
        src = eidx[e];
        tgt = eidx[N_EDGES + e];
    }

    const float4* urow = (const float4*)(g_UV + (size_t)src * 128);       // u half: [0..16)
    const float4* vrow = (const float4*)(g_UV + (size_t)tgt * 128) + 16;  // v half: [0..16)
    float4 u0 = urow[s];        // cols 4s   .. 4s+3
    float4 u1 = urow[8 + s];    // cols 32+4s .. 32+4s+3
    float4 v0 = vrow[s];
    float4 v1 = vrow[8 + s];

    float4 bb0 = *(const float4*)(sb1 + s * 4);
    float4 bb1 = *(const float4*)(sb1 + 32 + s * 4);
    float4 w0  = *(const float4*)(sw2 + s * 4);
    float4 w1  = *(const float4*)(sw2 + 32 + s * 4);

    float p = 0.f;
    {
        float z;
        z = fmaxf(u0.x + v0.x + bb0.x, 0.f); p = fmaf(z, w0.x, p);
        z = fmaxf(u0.y + v0.y + bb0.y, 0.f); p = fmaf(z, w0.y, p);
        z = fmaxf(u0.z + v0.z + bb0.z, 0.f); p = fmaf(z, w0.z, p);
        z = fmaxf(u0.w + v0.w + bb0.w, 0.f); p = fmaf(z, w0.w, p);
        z = fmaxf(u1.x + v1.x + bb1.x, 0.f); p = fmaf(z, w1.x, p);
        z = fmaxf(u1.y + v1.y + bb1.y, 0.f); p = fmaf(z, w1.y, p);
        z = fmaxf(u1.z + v1.z + bb1.z, 0.f); p = fmaf(z, w1.z, p);
        z = fmaxf(u1.w + v1.w + bb1.w, 0.f); p = fmaf(z, w1.w, p);
    }

    // reduce over the 8-lane group
    p += __shfl_xor_sync(0xFFFFFFFFu, p, 4);
    p += __shfl_xor_sync(0xFFFFFFFFu, p, 2);
    p += __shfl_xor_sync(0xFFFFFFFFu, p, 1);

    if (s == 0) out[e] = p + sb2;
}

// ---------------------------------------------------------------------------
extern "C" void kernel_launch(void* const* d_in, const int* in_sizes, int n_in,
                              void* d_out, int out_size) {
    const float* emb  = (const float*)d_in[0];
    const void*  eidx = d_in[1];
    const float* W1   = (const float*)d_in[2];
    const float* b1   = (const float*)d_in[3];
    const float* W2   = (const float*)d_in[4];
    const float* b2   = (const float*)d_in[5];
    float*       out  = (float*)d_out;

    cudaFuncSetAttribute(precompute_uv_kernel,
                         cudaFuncAttributeMaxDynamicSharedMemorySize,
                         128 * 128 * sizeof(float));

    // Kernel 1: 12500 warps (8 nodes each) -> 1563 blocks of 256 threads
    // (block 0 also detects the edge_index dtype)
    {
        int warps = (N_NODES + 7) / 8;
        int blocks = (warps * 32 + 255) / 256;
        precompute_uv_kernel<<<blocks, 256, 128 * 128 * sizeof(float)>>>(
            emb, W1, (const int*)eidx);
    }

    // Kernel 2: 8 threads per edge
    {
        long long threads = (long long)N_EDGES * 8;
        int blocks = (int)((threads + 255) / 256);
        edge_score_kernel<<<blocks, 256>>>(eidx, b1, W2, b2, out);
    }
}